// round 15
// baseline (speedup 1.0000x reference)
#include <cuda_runtime.h>
#include <cuda_bf16.h>
#include <cuda_fp16.h>
#include <cstdint>
#include <cstddef>

// ---------------- problem constants ----------------
#define B_   32
#define C_   256
#define H_   56
#define W_   56
#define OC_  256
#define HID_ 65
#define K_   4
#define HW_  3136
#define HP_  58                         // padded spatial (56+2)
#define KDIM 2304                       // 9 taps * 256 ch
#define SPATIAL_OUT ((size_t)B_*OC_*H_*W_)
#define NTILE 25                        // ceil(3136/128) pixel tiles

// ---------------- device scratch (no runtime allocation) ----------------
__device__ float g_pooled[B_*C_];
__device__ int   g_expert[B_];
__device__ __align__(16) __half g_wA[(size_t)K_*OC_*KDIM];    // [e][oc][t*256+c] integer values
__device__ __align__(16) __half g_xh[(size_t)B_*HP_*HP_*C_];  // [b][py][px][c] fp16

// ---------------- PTX helpers (arch-agnostic: sm_80+) ----------------
__device__ __forceinline__ uint32_t s2u(const void* p) {
    uint32_t a;
    asm("{ .reg .u64 t; cvta.to.shared.u64 t, %1; cvt.u32.u64 %0, t; }" : "=r"(a) : "l"(p));
    return a;
}
__device__ __forceinline__ void cpa16(uint32_t saddr, const void* g) {
    asm volatile("cp.async.ca.shared.global [%0], [%1], 16;" :: "r"(saddr), "l"(g) : "memory");
}
__device__ __forceinline__ void cpa_commit() {
    asm volatile("cp.async.commit_group;" ::: "memory");
}
template<int N>
__device__ __forceinline__ void cpa_wait() {
    asm volatile("cp.async.wait_group %0;" :: "n"(N) : "memory");
}
__device__ __forceinline__ void ldm_x4(uint32_t& r0, uint32_t& r1, uint32_t& r2, uint32_t& r3,
                                       uint32_t a) {
    asm volatile("ldmatrix.sync.aligned.m8n8.x4.shared.b16 {%0,%1,%2,%3}, [%4];"
                 : "=r"(r0), "=r"(r1), "=r"(r2), "=r"(r3) : "r"(a));
}
__device__ __forceinline__ void mma16816(float* d, const uint32_t* a, const uint32_t* b) {
    asm volatile("mma.sync.aligned.m16n8k16.row.col.f32.f16.f16.f32 "
                 "{%0,%1,%2,%3},{%4,%5,%6,%7},{%8,%9},{%0,%1,%2,%3};"
                 : "+f"(d[0]), "+f"(d[1]), "+f"(d[2]), "+f"(d[3])
                 : "r"(a[0]), "r"(a[1]), "r"(a[2]), "r"(a[3]), "r"(b[0]), "r"(b[1]));
}

// ---------------------------------------------------------------------------
// 1) Global average pool
// ---------------------------------------------------------------------------
__global__ void pool_kernel(const float* __restrict__ x) {
    int bc = blockIdx.x;
    const float* p = x + (size_t)bc * HW_;
    float s = 0.f;
    for (int i = threadIdx.x; i < HW_; i += 256) s += p[i];
    #pragma unroll
    for (int o = 16; o; o >>= 1) s += __shfl_down_sync(0xffffffffu, s, o);
    __shared__ float sm[8];
    if ((threadIdx.x & 31) == 0) sm[threadIdx.x >> 5] = s;
    __syncthreads();
    if (threadIdx.x == 0) {
        float t = 0.f;
        #pragma unroll
        for (int i = 0; i < 8; i++) t += sm[i];
        g_pooled[bc] = t * (1.0f / (float)HW_);
    }
}

// ---------------------------------------------------------------------------
// 2) Attention MLP + argmax expert select + raw logits
// ---------------------------------------------------------------------------
__global__ void attn_kernel(const float* __restrict__ w_fc1,
                            const float* __restrict__ w_fc2,
                            const float* __restrict__ b_fc2,
                            float* __restrict__ raw_out) {
    int b = blockIdx.x;
    __shared__ float ps[C_];
    __shared__ float hs[HID_];
    int tid = threadIdx.x;
    for (int i = tid; i < C_; i += 128) ps[i] = g_pooled[b*C_ + i];
    __syncthreads();
    if (tid < HID_) {
        const float* w = w_fc1 + tid * C_;
        float s = 0.f;
        for (int c = 0; c < C_; c++) s = fmaf(ps[c], w[c], s);
        hs[tid] = fmaxf(s, 0.f);
    }
    __syncthreads();
    if (tid == 0) {
        int best = 0; float bv = -3.4e38f;
        for (int k = 0; k < K_; k++) {
            const float* w = w_fc2 + k * HID_;
            float s = b_fc2[k];
            for (int j = 0; j < HID_; j++) s = fmaf(hs[j], w[j], s);
            raw_out[b*K_ + k] = s;
            if (s > bv) { bv = s; best = k; }
        }
        g_expert[b] = best;
    }
}

// ---------------------------------------------------------------------------
// 3) Weight quantize: one (k,oc) row per block, SMEM transpose, coalesced.
// ---------------------------------------------------------------------------
__global__ void quantw_kernel(const float* __restrict__ w,
                              const float* __restrict__ alpha) {
    __shared__ float smbuf[KDIM];
    const int bx = blockIdx.x, tid = threadIdx.x;
    const int k = bx >> 8;              // bx = k*256 + oc
    const int oc = bx & 255;
    const float a = alpha[k];
    const float* rw = w + (size_t)bx * KDIM;
    #pragma unroll
    for (int j = 0; j < 9; j++) {
        int i = tid * 9 + j;            // covers 0..2303 exactly
        smbuf[i] = rw[i] / a;           // layout c*9+t
    }
    __syncthreads();
    __half* dst = g_wA + (size_t)bx * KDIM;
    #pragma unroll
    for (int m = tid, it = 0; it < 9; m += 256, it++) {
        int t = m >> 8, c = m & 255;
        float d = smbuf[c * 9 + t];
        if (oc == 0 && m == 0) {        // only flat element [k,0] is clamped
            if      (k == 0) d = fminf(fmaxf(d, -2.f), 1.f);
            else if (k == 1) d = fminf(fmaxf(d, -4.f), 3.f);
            else if (k == 2) d = fminf(fmaxf(d, -8.f), 7.f);
        }
        dst[m] = __float2half(rintf(d));
    }
}

// ---------------------------------------------------------------------------
// 4) x transpose/pad row -> fp16 channels-last (incl. border zeroing)
// ---------------------------------------------------------------------------
__global__ void xprep_kernel(const float* __restrict__ x) {
    __shared__ float smbuf[64 * 57];
    const int bx = blockIdx.x, tid = threadIdx.x;
    const int b  = bx / HP_;
    const int yp = bx - b * HP_;                 // padded row 0..57
    __half* rowp = g_xh + (((size_t)b * HP_ + yp) * HP_) * C_;
    if (yp == 0 || yp == HP_ - 1) {
        for (int i = tid; i < HP_ * C_; i += 256) rowp[i] = __float2half(0.f);
        return;
    }
    for (int i = tid; i < 2 * C_; i += 256) {    // left/right halo columns
        int px = (i < C_) ? 0 : (HP_ - 1);
        rowp[(size_t)px * C_ + (i & (C_ - 1))] = __float2half(0.f);
    }
    const int y = yp - 1;
    for (int cb = 0; cb < 4; cb++) {
        __syncthreads();
        for (int idx = tid; idx < 64 * 56; idx += 256) {
            int i = idx / 56, j = idx - i * 56;
            smbuf[i * 57 + j] = x[((size_t)(b * C_ + cb * 64 + i)) * HW_ + y * W_ + j];
        }
        __syncthreads();
        for (int idx = tid; idx < 64 * 56; idx += 256) {
            int c = idx & 63, p = idx >> 6;
            rowp[(size_t)(p + 1) * C_ + cb * 64 + c] = __float2half(smbuf[c * 57 + p]);
        }
    }
}

// ---------------------------------------------------------------------------
// 5) mma.sync implicit-GEMM conv (fp16 operands, fp32 accumulate).
//    CTA: 256 threads, tile 128 oc x 128 px; 8 warps as 2(M)x4(N), 64x32 each.
//    K = 36 chunks of 64.  3-stage cp.async ring (96 KB) -> 2 CTAs/SM
//    (4 warps/SMSP), ONE sync per chunk.
// ---------------------------------------------------------------------------
#define CHUNK_BYTES 32768                      // A 16K + B 16K per stage
#define NSTAGE 3
#define SMEM_CONV (NSTAGE * CHUNK_BYTES)       // 96 KB
#define NCHUNK 36

__global__ void __launch_bounds__(256, 2)
conv_kernel(const float* __restrict__ bias_w,
            const float* __restrict__ alpha,
            float* __restrict__ out) {
    extern __shared__ __align__(16) char smem[];
    const uint32_t sbase = s2u(smem);
    const int tid  = threadIdx.x;
    const int lane = tid & 31, wid = tid >> 5;
    const int wm   = wid & 1;                  // M half (64 oc)
    const int wn   = wid >> 1;                 // N quarter (32 px)
    const int tile0 = blockIdx.x * 128;
    const int ocb  = blockIdx.y;
    const int b    = blockIdx.z;
    const int e    = g_expert[b];

    // ---- loader addressing: 2 threads/row, 4 uint4 each, for A and B ----
    const int lrow = tid >> 1;                 // 0..127
    const int lu0  = (tid & 1) * 4;
    const __half* gA_row = g_wA + ((size_t)(e * OC_ + ocb * 128 + lrow)) * KDIM;
    int pix = tile0 + lrow; if (pix > HW_ - 1) pix = HW_ - 1;
    int py = pix / W_, px = pix - py * W_;
    const size_t xoff = (((size_t)b * HP_ + py) * HP_ + px) * C_;
    const uint32_t sA_wr = sbase + lrow * 128;
    const uint32_t sB_wr = sbase + 16384 + lrow * 128;
    const int swz = lrow & 7;

    #define LOAD_CHUNK(CH, D) do {                                              \
        int _t = (CH) >> 2, _q = (CH) & 3;                                      \
        const uint4* _ga = (const uint4*)(gA_row + _t * C_ + _q * 64);          \
        const uint4* _gb = (const uint4*)(g_xh + xoff                           \
                                 + ((_t / 3) * HP_ + (_t % 3)) * C_ + _q * 64); \
        uint32_t _ao = sA_wr + (D) * CHUNK_BYTES;                               \
        uint32_t _bo = sB_wr + (D) * CHUNK_BYTES;                               \
        _Pragma("unroll")                                                       \
        for (int _u = lu0; _u < lu0 + 4; _u++) {                                \
            cpa16(_ao + (uint32_t)((_u ^ swz) << 4), _ga + _u);                 \
            cpa16(_bo + (uint32_t)((_u ^ swz) << 4), _gb + _u);                 \
        }                                                                        \
    } while (0)

    float acc[4][4][4];
    #pragma unroll
    for (int i = 0; i < 4; i++)
        #pragma unroll
        for (int j = 0; j < 4; j++)
            #pragma unroll
            for (int f = 0; f < 4; f++) acc[i][j][f] = 0.f;

    // ---- ldmatrix lane addressing ----
    const int a_r  = (lane & 7) + ((lane >> 3) & 1) * 8;
    const int a_kb = (lane >> 4) * 16;
    const int b_r  = (lane & 7) + (lane >> 4) * 8;
    const int b_kb = ((lane >> 3) & 1) * 16;
    const int a_row0 = wm * 64 + a_r;
    const int b_row0 = wn * 32 + b_r;

    LOAD_CHUNK(0, 0); cpa_commit();
    LOAD_CHUNK(1, 1); cpa_commit();

    #pragma unroll 1
    for (int ch = 0; ch < NCHUNK; ch++) {
        const int buf = ch % NSTAGE;
        if      (ch + 1 < NCHUNK) cpa_wait<1>();
        else                      cpa_wait<0>();
        // ONE barrier: chunk `ch` visible to all warps AND all reads of the
        // buffer that load ch+2 will overwrite are retired.
        __syncthreads();
        if (ch + 2 < NCHUNK) { LOAD_CHUNK(ch + 2, (ch + 2) % NSTAGE); cpa_commit(); }

        const uint32_t sA = sbase + buf * CHUNK_BYTES;
        const uint32_t sB = sA + 16384;
        #pragma unroll
        for (int kk = 0; kk < 4; kk++) {
            uint32_t a[4][4];
            #pragma unroll
            for (int mi = 0; mi < 4; mi++) {
                int row = a_row0 + mi * 16;
                int kb  = kk * 32 + a_kb;
                ldm_x4(a[mi][0], a[mi][1], a[mi][2], a[mi][3],
                       sA + row * 128 + (kb ^ ((row & 7) << 4)));
            }
            #pragma unroll
            for (int pr = 0; pr < 2; pr++) {
                uint32_t bb[4];
                int nrow = b_row0 + pr * 16;
                int kb   = kk * 32 + b_kb;
                ldm_x4(bb[0], bb[1], bb[2], bb[3],
                       sB + nrow * 128 + (kb ^ ((nrow & 7) << 4)));
                #pragma unroll
                for (int mi = 0; mi < 4; mi++) {
                    mma16816(acc[mi][pr * 2],     a[mi], bb);
                    mma16816(acc[mi][pr * 2 + 1], a[mi], bb + 2);
                }
            }
        }
    }

    // ---- epilogue: alpha * acc + bias, direct float2 stores ----
    const float al = alpha[e];
    const int qn = lane & 3, qm = lane >> 2;
    #pragma unroll
    for (int mi = 0; mi < 4; mi++) {
        int oc0 = ocb * 128 + wm * 64 + mi * 16 + qm;
        float bv0 = bias_w[e * OC_ + oc0];
        float bv1 = bias_w[e * OC_ + oc0 + 8];
        #pragma unroll
        for (int ni = 0; ni < 4; ni++) {
            int p = tile0 + wn * 32 + ni * 8 + qn * 2;
            if (p < HW_) {
                float2 v0, v1;
                v0.x = acc[mi][ni][0] * al + bv0;
                v0.y = acc[mi][ni][1] * al + bv0;
                v1.x = acc[mi][ni][2] * al + bv1;
                v1.y = acc[mi][ni][3] * al + bv1;
                *(float2*)(out + ((size_t)(b * OC_ + oc0)) * HW_ + p)     = v0;
                *(float2*)(out + ((size_t)(b * OC_ + oc0 + 8)) * HW_ + p) = v1;
            }
        }
    }
}

// ---------------------------------------------------------------------------
extern "C" void kernel_launch(void* const* d_in, const int* in_sizes, int n_in,
                              void* d_out, int out_size) {
    const float* x      = (const float*)d_in[0];
    const float* w_fc1  = (const float*)d_in[1];
    const float* w_fc2  = (const float*)d_in[2];
    const float* b_fc2  = (const float*)d_in[3];
    const float* alpha  = (const float*)d_in[4];
    const float* weight = (const float*)d_in[5];
    const float* bias_w = (const float*)d_in[6];
    float* out = (float*)d_out;
    float* raw_out = out + SPATIAL_OUT;

    pool_kernel<<<B_ * C_, 256>>>(x);                          // 1
    attn_kernel<<<B_, 128>>>(w_fc1, w_fc2, b_fc2, raw_out);    // 2
    quantw_kernel<<<K_ * OC_, 256>>>(weight, alpha);           // 3
    xprep_kernel<<<B_ * HP_, 256>>>(x);                        // 4

    cudaFuncSetAttribute(conv_kernel, cudaFuncAttributeMaxDynamicSharedMemorySize, SMEM_CONV);
    conv_kernel<<<dim3(NTILE, 2, B_), 256, SMEM_CONV>>>(bias_w, alpha, out); // 5
}

// round 16
// speedup vs baseline: 1.5801x; 1.5801x over previous
#include <cuda_runtime.h>
#include <cuda_bf16.h>
#include <cuda_fp16.h>
#include <cstdint>
#include <cstddef>

// ---------------- problem constants ----------------
#define B_   32
#define C_   256
#define H_   56
#define W_   56
#define OC_  256
#define HID_ 65
#define K_   4
#define HW_  3136
#define HP_  58                         // padded spatial (56+2)
#define KDIM 2304                       // 9 taps * 256 ch
#define SPATIAL_OUT ((size_t)B_*OC_*H_*W_)
#define NTILE 25                        // ceil(3136/128) pixel tiles

// ---------------- device scratch (no runtime allocation) ----------------
__device__ float g_rowsum[(size_t)B_*H_*C_];   // [b][y][c] per-row channel sums
__device__ int   g_expert[B_];
__device__ __align__(16) __half g_wA[(size_t)K_*OC_*KDIM];    // [e][oc][t*256+c] integer values
__device__ __align__(16) __half g_xh[(size_t)B_*HP_*HP_*C_];  // [b][py][px][c] fp16

// ---------------- PTX helpers (arch-agnostic: sm_80+) ----------------
__device__ __forceinline__ uint32_t s2u(const void* p) {
    uint32_t a;
    asm("{ .reg .u64 t; cvta.to.shared.u64 t, %1; cvt.u32.u64 %0, t; }" : "=r"(a) : "l"(p));
    return a;
}
__device__ __forceinline__ void cpa16(uint32_t saddr, const void* g) {
    asm volatile("cp.async.ca.shared.global [%0], [%1], 16;" :: "r"(saddr), "l"(g) : "memory");
}
__device__ __forceinline__ void cpa_commit() {
    asm volatile("cp.async.commit_group;" ::: "memory");
}
template<int N>
__device__ __forceinline__ void cpa_wait() {
    asm volatile("cp.async.wait_group %0;" :: "n"(N) : "memory");
}
__device__ __forceinline__ void ldm_x4(uint32_t& r0, uint32_t& r1, uint32_t& r2, uint32_t& r3,
                                       uint32_t a) {
    asm volatile("ldmatrix.sync.aligned.m8n8.x4.shared.b16 {%0,%1,%2,%3}, [%4];"
                 : "=r"(r0), "=r"(r1), "=r"(r2), "=r"(r3) : "r"(a));
}
__device__ __forceinline__ void mma16816(float* d, const uint32_t* a, const uint32_t* b) {
    asm volatile("mma.sync.aligned.m16n8k16.row.col.f32.f16.f16.f32 "
                 "{%0,%1,%2,%3},{%4,%5,%6,%7},{%8,%9},{%0,%1,%2,%3};"
                 : "+f"(d[0]), "+f"(d[1]), "+f"(d[2]), "+f"(d[3])
                 : "r"(a[0]), "r"(a[1]), "r"(a[2]), "r"(a[3]), "r"(b[0]), "r"(b[1]));
}

// ---------------------------------------------------------------------------
// 1) x transpose/pad row -> fp16 channels-last, FUSED with per-row channel
//    sums for the global average pool (no separate pool pass over x).
// ---------------------------------------------------------------------------
__global__ void xprep_kernel(const float* __restrict__ x) {
    __shared__ float smbuf[64 * 57];
    const int bx = blockIdx.x, tid = threadIdx.x;
    const int b  = bx / HP_;
    const int yp = bx - b * HP_;                 // padded row 0..57
    __half* rowp = g_xh + (((size_t)b * HP_ + yp) * HP_) * C_;
    if (yp == 0 || yp == HP_ - 1) {
        for (int i = tid; i < HP_ * C_; i += 256) rowp[i] = __float2half(0.f);
        return;
    }
    for (int i = tid; i < 2 * C_; i += 256) {    // left/right halo columns
        int px = (i < C_) ? 0 : (HP_ - 1);
        rowp[(size_t)px * C_ + (i & (C_ - 1))] = __float2half(0.f);
    }
    const int y = yp - 1;
    float* rs = g_rowsum + ((size_t)b * H_ + y) * C_;
    for (int cb = 0; cb < 4; cb++) {
        __syncthreads();
        for (int idx = tid; idx < 64 * 56; idx += 256) {
            int i = idx / 56, j = idx - i * 56;
            smbuf[i * 57 + j] = x[((size_t)(b * C_ + cb * 64 + i)) * HW_ + y * W_ + j];
        }
        __syncthreads();
        for (int idx = tid; idx < 64 * 56; idx += 256) {
            int c = idx & 63, p = idx >> 6;
            rowp[(size_t)(p + 1) * C_ + cb * 64 + c] = __float2half(smbuf[c * 57 + p]);
        }
        if (tid < 64) {                          // per-row channel sum (stride-57: conflict-free)
            float s = 0.f;
            #pragma unroll 8
            for (int p = 0; p < 56; p++) s += smbuf[tid * 57 + p];
            rs[cb * 64 + tid] = s;
        }
    }
}

// ---------------------------------------------------------------------------
// 2) Attention MLP (pool finished from row sums) + argmax expert + raw logits
// ---------------------------------------------------------------------------
__global__ void attn_kernel(const float* __restrict__ w_fc1,
                            const float* __restrict__ w_fc2,
                            const float* __restrict__ b_fc2,
                            float* __restrict__ raw_out) {
    int b = blockIdx.x;
    __shared__ float ps[C_];
    __shared__ float hs[HID_];
    int tid = threadIdx.x;                       // 128 threads
    const float* rsb = g_rowsum + (size_t)b * H_ * C_;
    for (int i = tid; i < C_; i += 128) {
        float s = 0.f;
        for (int y = 0; y < H_; y++) s += rsb[y * C_ + i];
        ps[i] = s * (1.0f / (float)HW_);
    }
    __syncthreads();
    if (tid < HID_) {
        const float* w = w_fc1 + tid * C_;
        float s = 0.f;
        for (int c = 0; c < C_; c++) s = fmaf(ps[c], w[c], s);
        hs[tid] = fmaxf(s, 0.f);
    }
    __syncthreads();
    if (tid == 0) {
        int best = 0; float bv = -3.4e38f;
        for (int k = 0; k < K_; k++) {
            const float* w = w_fc2 + k * HID_;
            float s = b_fc2[k];
            for (int j = 0; j < HID_; j++) s = fmaf(hs[j], w[j], s);
            raw_out[b*K_ + k] = s;
            if (s > bv) { bv = s; best = k; }
        }
        g_expert[b] = best;
    }
}

// ---------------------------------------------------------------------------
// 3) Weight quantize: one (k,oc) row per block, SMEM transpose, coalesced.
// ---------------------------------------------------------------------------
__global__ void quantw_kernel(const float* __restrict__ w,
                              const float* __restrict__ alpha) {
    __shared__ float smbuf[KDIM];
    const int bx = blockIdx.x, tid = threadIdx.x;
    const int k = bx >> 8;              // bx = k*256 + oc
    const int oc = bx & 255;
    const float a = alpha[k];
    const float* rw = w + (size_t)bx * KDIM;
    #pragma unroll
    for (int j = 0; j < 9; j++) {
        int i = tid * 9 + j;            // covers 0..2303 exactly
        smbuf[i] = rw[i] / a;           // layout c*9+t
    }
    __syncthreads();
    __half* dst = g_wA + (size_t)bx * KDIM;
    #pragma unroll
    for (int m = tid, it = 0; it < 9; m += 256, it++) {
        int t = m >> 8, c = m & 255;
        float d = smbuf[c * 9 + t];
        if (oc == 0 && m == 0) {        // only flat element [k,0] is clamped
            if      (k == 0) d = fminf(fmaxf(d, -2.f), 1.f);
            else if (k == 1) d = fminf(fmaxf(d, -4.f), 3.f);
            else if (k == 2) d = fminf(fmaxf(d, -8.f), 7.f);
        }
        dst[m] = __float2half(rintf(d));
    }
}

// ---------------------------------------------------------------------------
// 4) mma.sync implicit-GEMM conv — the R6 (582-era) configuration verbatim:
//    CTA 256 thr, tile 128 oc x 128 px, 8 warps 2(M)x4(N), warp 64x32.
//    3-stage cp.async ring (96 KB) -> 2 CTAs/SM.  Pipeline discipline:
//    issue load ch+2, commit, wait<2> (retire ONLY chunk ch), sync, compute,
//    sync.
// ---------------------------------------------------------------------------
#define CHUNK_BYTES 32768                      // A 16K + B 16K per stage
#define NSTAGE 3
#define SMEM_CONV (NSTAGE * CHUNK_BYTES)       // 96 KB
#define NCHUNK 36

__global__ void __launch_bounds__(256, 2)
conv_kernel(const float* __restrict__ bias_w,
            const float* __restrict__ alpha,
            float* __restrict__ out) {
    extern __shared__ __align__(16) char smem[];
    const uint32_t sbase = s2u(smem);
    const int tid  = threadIdx.x;
    const int lane = tid & 31, wid = tid >> 5;
    const int wm   = wid & 1;                  // M half (64 oc)
    const int wn   = wid >> 1;                 // N quarter (32 px)
    const int tile0 = blockIdx.x * 128;
    const int ocb  = blockIdx.y;
    const int b    = blockIdx.z;
    const int e    = g_expert[b];

    // ---- loader addressing: 2 threads/row, 4 uint4 each, for A and B ----
    const int lrow = tid >> 1;                 // 0..127
    const int lu0  = (tid & 1) * 4;
    const __half* gA_row = g_wA + ((size_t)(e * OC_ + ocb * 128 + lrow)) * KDIM;
    int pix = tile0 + lrow; if (pix > HW_ - 1) pix = HW_ - 1;
    int py = pix / W_, px = pix - py * W_;
    const size_t xoff = (((size_t)b * HP_ + py) * HP_ + px) * C_;
    const uint32_t sA_wr = sbase + lrow * 128;
    const uint32_t sB_wr = sbase + 16384 + lrow * 128;
    const int swz = lrow & 7;

    #define LOAD_CHUNK(CH, D) do {                                              \
        int _t = (CH) >> 2, _q = (CH) & 3;                                      \
        const uint4* _ga = (const uint4*)(gA_row + _t * C_ + _q * 64);          \
        const uint4* _gb = (const uint4*)(g_xh + xoff                           \
                                 + ((_t / 3) * HP_ + (_t % 3)) * C_ + _q * 64); \
        uint32_t _ao = sA_wr + (D) * CHUNK_BYTES;                               \
        uint32_t _bo = sB_wr + (D) * CHUNK_BYTES;                               \
        _Pragma("unroll")                                                       \
        for (int _u = lu0; _u < lu0 + 4; _u++) {                                \
            cpa16(_ao + (uint32_t)((_u ^ swz) << 4), _ga + _u);                 \
            cpa16(_bo + (uint32_t)((_u ^ swz) << 4), _gb + _u);                 \
        }                                                                        \
    } while (0)

    float acc[4][4][4];
    #pragma unroll
    for (int i = 0; i < 4; i++)
        #pragma unroll
        for (int j = 0; j < 4; j++)
            #pragma unroll
            for (int f = 0; f < 4; f++) acc[i][j][f] = 0.f;

    // ---- ldmatrix lane addressing ----
    const int a_r  = (lane & 7) + ((lane >> 3) & 1) * 8;
    const int a_kb = (lane >> 4) * 16;
    const int b_r  = (lane & 7) + (lane >> 4) * 8;
    const int b_kb = ((lane >> 3) & 1) * 16;
    const int a_row0 = wm * 64 + a_r;
    const int b_row0 = wn * 32 + b_r;

    LOAD_CHUNK(0, 0); cpa_commit();
    LOAD_CHUNK(1, 1); cpa_commit();

    #pragma unroll 1
    for (int ch = 0; ch < NCHUNK; ch++) {
        const int buf = ch % NSTAGE;
        if (ch + 2 < NCHUNK) { LOAD_CHUNK(ch + 2, (ch + 2) % NSTAGE); cpa_commit(); cpa_wait<2>(); }
        else if (ch + 1 < NCHUNK) { cpa_wait<1>(); }
        else { cpa_wait<0>(); }
        __syncthreads();

        const uint32_t sA = sbase + buf * CHUNK_BYTES;
        const uint32_t sB = sA + 16384;
        #pragma unroll
        for (int kk = 0; kk < 4; kk++) {
            uint32_t a[4][4];
            #pragma unroll
            for (int mi = 0; mi < 4; mi++) {
                int row = a_row0 + mi * 16;
                int kb  = kk * 32 + a_kb;
                ldm_x4(a[mi][0], a[mi][1], a[mi][2], a[mi][3],
                       sA + row * 128 + (kb ^ ((row & 7) << 4)));
            }
            #pragma unroll
            for (int pr = 0; pr < 2; pr++) {
                uint32_t bb[4];
                int nrow = b_row0 + pr * 16;
                int kb   = kk * 32 + b_kb;
                ldm_x4(bb[0], bb[1], bb[2], bb[3],
                       sB + nrow * 128 + (kb ^ ((nrow & 7) << 4)));
                #pragma unroll
                for (int mi = 0; mi < 4; mi++) {
                    mma16816(acc[mi][pr * 2],     a[mi], bb);
                    mma16816(acc[mi][pr * 2 + 1], a[mi], bb + 2);
                }
            }
        }
        __syncthreads();
    }

    // ---- epilogue: alpha * acc + bias, direct float2 stores ----
    const float al = alpha[e];
    const int qn = lane & 3, qm = lane >> 2;
    #pragma unroll
    for (int mi = 0; mi < 4; mi++) {
        int oc0 = ocb * 128 + wm * 64 + mi * 16 + qm;
        float bv0 = bias_w[e * OC_ + oc0];
        float bv1 = bias_w[e * OC_ + oc0 + 8];
        #pragma unroll
        for (int ni = 0; ni < 4; ni++) {
            int p = tile0 + wn * 32 + ni * 8 + qn * 2;
            if (p < HW_) {
                float2 v0, v1;
                v0.x = acc[mi][ni][0] * al + bv0;
                v0.y = acc[mi][ni][1] * al + bv0;
                v1.x = acc[mi][ni][2] * al + bv1;
                v1.y = acc[mi][ni][3] * al + bv1;
                *(float2*)(out + ((size_t)(b * OC_ + oc0)) * HW_ + p)     = v0;
                *(float2*)(out + ((size_t)(b * OC_ + oc0 + 8)) * HW_ + p) = v1;
            }
        }
    }
}

// ---------------------------------------------------------------------------
extern "C" void kernel_launch(void* const* d_in, const int* in_sizes, int n_in,
                              void* d_out, int out_size) {
    const float* x      = (const float*)d_in[0];
    const float* w_fc1  = (const float*)d_in[1];
    const float* w_fc2  = (const float*)d_in[2];
    const float* b_fc2  = (const float*)d_in[3];
    const float* alpha  = (const float*)d_in[4];
    const float* weight = (const float*)d_in[5];
    const float* bias_w = (const float*)d_in[6];
    float* out = (float*)d_out;
    float* raw_out = out + SPATIAL_OUT;

    xprep_kernel<<<B_ * HP_, 256>>>(x);                        // 1 (x prep + row sums)
    attn_kernel<<<B_, 128>>>(w_fc1, w_fc2, b_fc2, raw_out);    // 2
    quantw_kernel<<<K_ * OC_, 256>>>(weight, alpha);           // 3

    cudaFuncSetAttribute(conv_kernel, cudaFuncAttributeMaxDynamicSharedMemorySize, SMEM_CONV);
    conv_kernel<<<dim3(NTILE, 2, B_), 256, SMEM_CONV>>>(bias_w, alpha, out); // 4 (profiled)
}

// round 17
// speedup vs baseline: 1.6730x; 1.0587x over previous
#include <cuda_runtime.h>
#include <cuda_bf16.h>
#include <cuda_fp16.h>
#include <cstdint>
#include <cstddef>

// ---------------- problem constants ----------------
#define B_   32
#define C_   256
#define H_   56
#define W_   56
#define OC_  256
#define HID_ 65
#define K_   4
#define HW_  3136
#define HP_  58                         // padded spatial (56+2)
#define KDIM 2304                       // 9 taps * 256 ch
#define SPATIAL_OUT ((size_t)B_*OC_*H_*W_)
#define NTILE 25                        // ceil(3136/128) pixel tiles

// ---------------- device scratch (no runtime allocation) ----------------
__device__ float g_rowsum[(size_t)B_*H_*C_];   // [b][y][c] per-row channel sums
__device__ int   g_expert[B_];
__device__ __align__(16) __half g_wA[(size_t)K_*OC_*KDIM];    // [e][oc][t*256+c] integer values
__device__ __align__(16) __half g_xh[(size_t)B_*HP_*HP_*C_];  // [b][py][px][c] fp16

// ---------------- PTX helpers (arch-agnostic: sm_80+) ----------------
__device__ __forceinline__ uint32_t s2u(const void* p) {
    uint32_t a;
    asm("{ .reg .u64 t; cvta.to.shared.u64 t, %1; cvt.u32.u64 %0, t; }" : "=r"(a) : "l"(p));
    return a;
}
__device__ __forceinline__ void cpa16(uint32_t saddr, const void* g) {
    // .cg: bypass L1 fill path — staged data has no L1 reuse
    asm volatile("cp.async.cg.shared.global [%0], [%1], 16;" :: "r"(saddr), "l"(g) : "memory");
}
__device__ __forceinline__ void cpa_commit() {
    asm volatile("cp.async.commit_group;" ::: "memory");
}
template<int N>
__device__ __forceinline__ void cpa_wait() {
    asm volatile("cp.async.wait_group %0;" :: "n"(N) : "memory");
}
__device__ __forceinline__ void ldm_x4(uint32_t& r0, uint32_t& r1, uint32_t& r2, uint32_t& r3,
                                       uint32_t a) {
    asm volatile("ldmatrix.sync.aligned.m8n8.x4.shared.b16 {%0,%1,%2,%3}, [%4];"
                 : "=r"(r0), "=r"(r1), "=r"(r2), "=r"(r3) : "r"(a));
}
__device__ __forceinline__ void mma16816(float* d, const uint32_t* a, const uint32_t* b) {
    asm volatile("mma.sync.aligned.m16n8k16.row.col.f32.f16.f16.f32 "
                 "{%0,%1,%2,%3},{%4,%5,%6,%7},{%8,%9},{%0,%1,%2,%3};"
                 : "+f"(d[0]), "+f"(d[1]), "+f"(d[2]), "+f"(d[3])
                 : "r"(a[0]), "r"(a[1]), "r"(a[2]), "r"(a[3]), "r"(b[0]), "r"(b[1]));
}

// ---------------------------------------------------------------------------
// 1) x transpose/pad -> fp16 channels-last, fused with per-row channel sums.
//    Grid: (4 cb-quarters, B*HP rows). One block = one (b, padded-row, 64-ch
//    quarter): load 64ch x 56px, transpose in SMEM, write channels-last,
//    emit 64 row-sums. No loop, two barriers.
// ---------------------------------------------------------------------------
__global__ void xprep_kernel(const float* __restrict__ x) {
    __shared__ float smbuf[64 * 57];
    const int cb  = blockIdx.x;                  // 0..3
    const int by  = blockIdx.y;                  // 0..B*HP-1
    const int b   = by / HP_;
    const int yp  = by - b * HP_;                // padded row 0..57
    const int tid = threadIdx.x;                 // 256 threads
    __half* rowp = g_xh + (((size_t)b * HP_ + yp) * HP_) * C_;
    if (yp == 0 || yp == HP_ - 1) {              // top/bottom halo rows: zero our quarter
        const int qn = HP_ * C_ / 4;             // 3712
        for (int i = tid; i < qn; i += 256) rowp[cb * qn + i] = __float2half(0.f);
        return;
    }
    if (cb == 0) {                               // left/right halo columns (once per row)
        for (int i = tid; i < 2 * C_; i += 256) {
            int px = (i < C_) ? 0 : (HP_ - 1);
            rowp[(size_t)px * C_ + (i & (C_ - 1))] = __float2half(0.f);
        }
    }
    const int y = yp - 1;
    // load 64 channels x 56 px (contiguous 224B per channel-row)
    for (int idx = tid; idx < 64 * 56; idx += 256) {
        int i = idx / 56, j = idx - i * 56;
        smbuf[i * 57 + j] = x[((size_t)(b * C_ + cb * 64 + i)) * HW_ + y * W_ + j];
    }
    __syncthreads();
    // transposed channels-last write (c fastest, 128B per px quarter)
    for (int idx = tid; idx < 64 * 56; idx += 256) {
        int c = idx & 63, p = idx >> 6;
        rowp[(size_t)(p + 1) * C_ + cb * 64 + c] = __float2half(smbuf[c * 57 + p]);
    }
    if (tid < 64) {                              // row sums (stride-57: conflict-free)
        float s = 0.f;
        #pragma unroll 8
        for (int p = 0; p < 56; p++) s += smbuf[tid * 57 + p];
        g_rowsum[((size_t)b * H_ + y) * C_ + cb * 64 + tid] = s;
    }
}

// ---------------------------------------------------------------------------
// 2) Attention MLP (pool finished from row sums) + argmax expert + raw logits
// ---------------------------------------------------------------------------
__global__ void attn_kernel(const float* __restrict__ w_fc1,
                            const float* __restrict__ w_fc2,
                            const float* __restrict__ b_fc2,
                            float* __restrict__ raw_out) {
    int b = blockIdx.x;
    __shared__ float ps[C_];
    __shared__ float hs[HID_];
    int tid = threadIdx.x;                       // 128 threads
    const float* rsb = g_rowsum + (size_t)b * H_ * C_;
    for (int i = tid; i < C_; i += 128) {
        float s = 0.f;
        for (int y = 0; y < H_; y++) s += rsb[y * C_ + i];
        ps[i] = s * (1.0f / (float)HW_);
    }
    __syncthreads();
    if (tid < HID_) {
        const float* w = w_fc1 + tid * C_;
        float s = 0.f;
        for (int c = 0; c < C_; c++) s = fmaf(ps[c], w[c], s);
        hs[tid] = fmaxf(s, 0.f);
    }
    __syncthreads();
    if (tid == 0) {
        int best = 0; float bv = -3.4e38f;
        for (int k = 0; k < K_; k++) {
            const float* w = w_fc2 + k * HID_;
            float s = b_fc2[k];
            for (int j = 0; j < HID_; j++) s = fmaf(hs[j], w[j], s);
            raw_out[b*K_ + k] = s;
            if (s > bv) { bv = s; best = k; }
        }
        g_expert[b] = best;
    }
}

// ---------------------------------------------------------------------------
// 3) Weight quantize: one (k,oc) row per block, SMEM transpose, coalesced.
// ---------------------------------------------------------------------------
__global__ void quantw_kernel(const float* __restrict__ w,
                              const float* __restrict__ alpha) {
    __shared__ float smbuf[KDIM];
    const int bx = blockIdx.x, tid = threadIdx.x;
    const int k = bx >> 8;              // bx = k*256 + oc
    const int oc = bx & 255;
    const float a = alpha[k];
    const float* rw = w + (size_t)bx * KDIM;
    #pragma unroll
    for (int j = 0; j < 9; j++) {
        int i = tid * 9 + j;            // covers 0..2303 exactly
        smbuf[i] = rw[i] / a;           // layout c*9+t
    }
    __syncthreads();
    __half* dst = g_wA + (size_t)bx * KDIM;
    #pragma unroll
    for (int m = tid, it = 0; it < 9; m += 256, it++) {
        int t = m >> 8, c = m & 255;
        float d = smbuf[c * 9 + t];
        if (oc == 0 && m == 0) {        // only flat element [k,0] is clamped
            if      (k == 0) d = fminf(fmaxf(d, -2.f), 1.f);
            else if (k == 1) d = fminf(fmaxf(d, -4.f), 3.f);
            else if (k == 2) d = fminf(fmaxf(d, -8.f), 7.f);
        }
        dst[m] = __float2half(rintf(d));
    }
}

// ---------------------------------------------------------------------------
// 4) mma.sync implicit-GEMM conv — R16 configuration (best measured):
//    CTA 256 thr, tile 128 oc x 128 px, 8 warps 2(M)x4(N), warp 64x32.
//    3-stage cp.async ring (96 KB) -> 2 CTAs/SM.  Pipeline discipline:
//    issue load ch+2, commit, wait<2> (retire ONLY chunk ch), sync, compute,
//    sync.
// ---------------------------------------------------------------------------
#define CHUNK_BYTES 32768                      // A 16K + B 16K per stage
#define NSTAGE 3
#define SMEM_CONV (NSTAGE * CHUNK_BYTES)       // 96 KB
#define NCHUNK 36

__global__ void __launch_bounds__(256, 2)
conv_kernel(const float* __restrict__ bias_w,
            const float* __restrict__ alpha,
            float* __restrict__ out) {
    extern __shared__ __align__(16) char smem[];
    const uint32_t sbase = s2u(smem);
    const int tid  = threadIdx.x;
    const int lane = tid & 31, wid = tid >> 5;
    const int wm   = wid & 1;                  // M half (64 oc)
    const int wn   = wid >> 1;                 // N quarter (32 px)
    const int tile0 = blockIdx.x * 128;
    const int ocb  = blockIdx.y;
    const int b    = blockIdx.z;
    const int e    = g_expert[b];

    // ---- loader addressing: 2 threads/row, 4 uint4 each, for A and B ----
    const int lrow = tid >> 1;                 // 0..127
    const int lu0  = (tid & 1) * 4;
    const __half* gA_row = g_wA + ((size_t)(e * OC_ + ocb * 128 + lrow)) * KDIM;
    int pix = tile0 + lrow; if (pix > HW_ - 1) pix = HW_ - 1;
    int py = pix / W_, px = pix - py * W_;
    const size_t xoff = (((size_t)b * HP_ + py) * HP_ + px) * C_;
    const uint32_t sA_wr = sbase + lrow * 128;
    const uint32_t sB_wr = sbase + 16384 + lrow * 128;
    const int swz = lrow & 7;

    #define LOAD_CHUNK(CH, D) do {                                              \
        int _t = (CH) >> 2, _q = (CH) & 3;                                      \
        const uint4* _ga = (const uint4*)(gA_row + _t * C_ + _q * 64);          \
        const uint4* _gb = (const uint4*)(g_xh + xoff                           \
                                 + ((_t / 3) * HP_ + (_t % 3)) * C_ + _q * 64); \
        uint32_t _ao = sA_wr + (D) * CHUNK_BYTES;                               \
        uint32_t _bo = sB_wr + (D) * CHUNK_BYTES;                               \
        _Pragma("unroll")                                                       \
        for (int _u = lu0; _u < lu0 + 4; _u++) {                                \
            cpa16(_ao + (uint32_t)((_u ^ swz) << 4), _ga + _u);                 \
            cpa16(_bo + (uint32_t)((_u ^ swz) << 4), _gb + _u);                 \
        }                                                                        \
    } while (0)

    float acc[4][4][4];
    #pragma unroll
    for (int i = 0; i < 4; i++)
        #pragma unroll
        for (int j = 0; j < 4; j++)
            #pragma unroll
            for (int f = 0; f < 4; f++) acc[i][j][f] = 0.f;

    // ---- ldmatrix lane addressing ----
    const int a_r  = (lane & 7) + ((lane >> 3) & 1) * 8;
    const int a_kb = (lane >> 4) * 16;
    const int b_r  = (lane & 7) + (lane >> 4) * 8;
    const int b_kb = ((lane >> 3) & 1) * 16;
    const int a_row0 = wm * 64 + a_r;
    const int b_row0 = wn * 32 + b_r;

    LOAD_CHUNK(0, 0); cpa_commit();
    LOAD_CHUNK(1, 1); cpa_commit();

    #pragma unroll 1
    for (int ch = 0; ch < NCHUNK; ch++) {
        const int buf = ch % NSTAGE;
        if (ch + 2 < NCHUNK) { LOAD_CHUNK(ch + 2, (ch + 2) % NSTAGE); cpa_commit(); cpa_wait<2>(); }
        else if (ch + 1 < NCHUNK) { cpa_wait<1>(); }
        else { cpa_wait<0>(); }
        __syncthreads();

        const uint32_t sA = sbase + buf * CHUNK_BYTES;
        const uint32_t sB = sA + 16384;
        #pragma unroll
        for (int kk = 0; kk < 4; kk++) {
            uint32_t a[4][4];
            #pragma unroll
            for (int mi = 0; mi < 4; mi++) {
                int row = a_row0 + mi * 16;
                int kb  = kk * 32 + a_kb;
                ldm_x4(a[mi][0], a[mi][1], a[mi][2], a[mi][3],
                       sA + row * 128 + (kb ^ ((row & 7) << 4)));
            }
            #pragma unroll
            for (int pr = 0; pr < 2; pr++) {
                uint32_t bb[4];
                int nrow = b_row0 + pr * 16;
                int kb   = kk * 32 + b_kb;
                ldm_x4(bb[0], bb[1], bb[2], bb[3],
                       sB + nrow * 128 + (kb ^ ((nrow & 7) << 4)));
                #pragma unroll
                for (int mi = 0; mi < 4; mi++) {
                    mma16816(acc[mi][pr * 2],     a[mi], bb);
                    mma16816(acc[mi][pr * 2 + 1], a[mi], bb + 2);
                }
            }
        }
        __syncthreads();
    }

    // ---- epilogue: alpha * acc + bias, direct float2 stores ----
    const float al = alpha[e];
    const int qn = lane & 3, qm = lane >> 2;
    #pragma unroll
    for (int mi = 0; mi < 4; mi++) {
        int oc0 = ocb * 128 + wm * 64 + mi * 16 + qm;
        float bv0 = bias_w[e * OC_ + oc0];
        float bv1 = bias_w[e * OC_ + oc0 + 8];
        #pragma unroll
        for (int ni = 0; ni < 4; ni++) {
            int p = tile0 + wn * 32 + ni * 8 + qn * 2;
            if (p < HW_) {
                float2 v0, v1;
                v0.x = acc[mi][ni][0] * al + bv0;
                v0.y = acc[mi][ni][1] * al + bv0;
                v1.x = acc[mi][ni][2] * al + bv1;
                v1.y = acc[mi][ni][3] * al + bv1;
                *(float2*)(out + ((size_t)(b * OC_ + oc0)) * HW_ + p)     = v0;
                *(float2*)(out + ((size_t)(b * OC_ + oc0 + 8)) * HW_ + p) = v1;
            }
        }
    }
}

// ---------------------------------------------------------------------------
extern "C" void kernel_launch(void* const* d_in, const int* in_sizes, int n_in,
                              void* d_out, int out_size) {
    const float* x      = (const float*)d_in[0];
    const float* w_fc1  = (const float*)d_in[1];
    const float* w_fc2  = (const float*)d_in[2];
    const float* b_fc2  = (const float*)d_in[3];
    const float* alpha  = (const float*)d_in[4];
    const float* weight = (const float*)d_in[5];
    const float* bias_w = (const float*)d_in[6];
    float* out = (float*)d_out;
    float* raw_out = out + SPATIAL_OUT;

    xprep_kernel<<<dim3(4, B_ * HP_), 256>>>(x);               // 1 (x prep + row sums)
    attn_kernel<<<B_, 128>>>(w_fc1, w_fc2, b_fc2, raw_out);    // 2
    quantw_kernel<<<K_ * OC_, 256>>>(weight, alpha);           // 3

    cudaFuncSetAttribute(conv_kernel, cudaFuncAttributeMaxDynamicSharedMemorySize, SMEM_CONV);
    conv_kernel<<<dim3(NTILE, 2, B_), 256, SMEM_CONV>>>(bias_w, alpha, out); // 4 (profiled)
}